// round 9
// baseline (speedup 1.0000x reference)
#include <cuda_runtime.h>
#include <cuda_bf16.h>
#include <cstdint>
#include <cstddef>

// ============================================================================
// CustomGaussianLayer: out[b,o] = sum_{i,g} exp(-0.5*z^2)*coeff[o,i,g]*w[o,i]
// Restructured as GEMM C[8192,512] = E[8192,4096] @ W2^T[4096,512] with
// split-bf16 3-term product (Ehi*Whi + Elo*Whi + Ehi*Wlo) fused into one GEMM
// of K_eff = 3*4096 = 12288 via segment-switched source pointers.
//
// NOTE: the harness lowers to PTX target sm_103 (no 'a'), so tcgen05/TMEM are
// unavailable. We use baseline-ISA tensor cores: mma.sync.m16n8k16.bf16 +
// ldmatrix + cp.async 4-stage pipeline.
// ============================================================================

#define DINL __device__ __forceinline__

constexpr int BATCH = 8192;
constexpr int ISZ   = 512;
constexpr int OSZ   = 512;
constexpr int K1    = ISZ * 8;            // 4096
constexpr int KROW_BYTES = K1 * 2;        // 8192 bytes per row (bf16)

// GEMM tiling
constexpr int TM = 128;
constexpr int TN = 128;
constexpr int KCH = 32;                   // K per stage (64 bytes per row)
constexpr int STAGES_PER_SEG = K1 / KCH;  // 128
constexpr int NITER = 3 * STAGES_PER_SEG; // 384
constexpr int PITCH = 80;                 // smem row pitch (bank-conflict-free)
constexpr int A_SMEM = TM * PITCH;        // 10240
constexpr int STAGE_BYTES = 2 * A_SMEM;   // 20480 (A then B)
constexpr int NSTAGE = 4;
constexpr int SMEM_TOTAL = NSTAGE * STAGE_BYTES; // 81920

// device scratch (static: no allocation allowed)
__device__ __nv_bfloat16 g_Ehi[(size_t)BATCH * K1];
__device__ __nv_bfloat16 g_Elo[(size_t)BATCH * K1];
__device__ __nv_bfloat16 g_Whi[(size_t)OSZ * K1];
__device__ __nv_bfloat16 g_Wlo[(size_t)OSZ * K1];

DINL uint32_t smem_u32(const void* p) {
    uint32_t a;
    asm("{ .reg .u64 t; cvta.to.shared.u64 t, %1; cvt.u32.u64 %0, t; }" : "=r"(a) : "l"(p));
    return a;
}

DINL void cp_async16(uint32_t dst, const void* src) {
    asm volatile("cp.async.cg.shared.global [%0], [%1], 16;" :: "r"(dst), "l"(src) : "memory");
}
DINL void cp_commit() { asm volatile("cp.async.commit_group;" ::: "memory"); }
DINL void cp_wait2()  { asm volatile("cp.async.wait_group 2;" ::: "memory"); }

DINL void ldsm_x4(uint32_t (&r)[4], uint32_t addr) {
    asm volatile("ldmatrix.sync.aligned.m8n8.x4.shared.b16 {%0,%1,%2,%3}, [%4];"
                 : "=r"(r[0]), "=r"(r[1]), "=r"(r[2]), "=r"(r[3]) : "r"(addr));
}

DINL void mma16816(float (&d)[4], const uint32_t (&a)[4], const uint32_t* b) {
    asm volatile(
        "mma.sync.aligned.m16n8k16.row.col.f32.bf16.bf16.f32 "
        "{%0,%1,%2,%3}, {%4,%5,%6,%7}, {%8,%9}, {%0,%1,%2,%3};"
        : "+f"(d[0]), "+f"(d[1]), "+f"(d[2]), "+f"(d[3])
        : "r"(a[0]), "r"(a[1]), "r"(a[2]), "r"(a[3]), "r"(b[0]), "r"(b[1]));
}

// ---------------- prep kernels ----------------
__global__ void prep_W(const float* __restrict__ w, const float* __restrict__ coef) {
    int idx = blockIdx.x * 256 + threadIdx.x;   // o*512 + i
    float wv = w[idx];
    const float4* cp = reinterpret_cast<const float4*>(coef + (size_t)idx * 8);
    float4 c0 = cp[0], c1 = cp[1];
    float v[8] = {c0.x, c0.y, c0.z, c0.w, c1.x, c1.y, c1.z, c1.w};
    unsigned short hi[8], lo[8];
#pragma unroll
    for (int g = 0; g < 8; g++) {
        float t = v[g] * wv;
        __nv_bfloat16 h = __float2bfloat16(t);
        float r = t - __bfloat162float(h);
        hi[g] = __bfloat16_as_ushort(h);
        lo[g] = __bfloat16_as_ushort(__float2bfloat16(r));
    }
    uint4 uh, ul;
    uh.x = hi[0] | ((uint32_t)hi[1] << 16); uh.y = hi[2] | ((uint32_t)hi[3] << 16);
    uh.z = hi[4] | ((uint32_t)hi[5] << 16); uh.w = hi[6] | ((uint32_t)hi[7] << 16);
    ul.x = lo[0] | ((uint32_t)lo[1] << 16); ul.y = lo[2] | ((uint32_t)lo[3] << 16);
    ul.z = lo[4] | ((uint32_t)lo[5] << 16); ul.w = lo[6] | ((uint32_t)lo[7] << 16);
    *reinterpret_cast<uint4*>(&g_Whi[(size_t)idx * 8]) = uh;
    *reinterpret_cast<uint4*>(&g_Wlo[(size_t)idx * 8]) = ul;
}

__global__ void prep_E(const float* __restrict__ x) {
    int idx = blockIdx.x * 256 + threadIdx.x;   // b*512 + i
    float xt = tanhf(x[idx]);
    unsigned short hi[8], lo[8];
#pragma unroll
    for (int g = 0; g < 8; g++) {
        float z = fmaf(7.0f, xt, 7.0f - 2.0f * (float)g);
        float e = __expf(-0.5f * z * z);
        __nv_bfloat16 h = __float2bfloat16(e);
        float r = e - __bfloat162float(h);
        hi[g] = __bfloat16_as_ushort(h);
        lo[g] = __bfloat16_as_ushort(__float2bfloat16(r));
    }
    uint4 uh, ul;
    uh.x = hi[0] | ((uint32_t)hi[1] << 16); uh.y = hi[2] | ((uint32_t)hi[3] << 16);
    uh.z = hi[4] | ((uint32_t)hi[5] << 16); uh.w = hi[6] | ((uint32_t)hi[7] << 16);
    ul.x = lo[0] | ((uint32_t)lo[1] << 16); ul.y = lo[2] | ((uint32_t)lo[3] << 16);
    ul.z = lo[4] | ((uint32_t)lo[5] << 16); ul.w = lo[6] | ((uint32_t)lo[7] << 16);
    *reinterpret_cast<uint4*>(&g_Ehi[(size_t)idx * 8]) = uh;
    *reinterpret_cast<uint4*>(&g_Elo[(size_t)idx * 8]) = ul;
}

// ---------------- GEMM kernel ----------------
// grid = (OSZ/TN = 4, BATCH/TM = 64), 256 threads, 2 CTAs/SM -> 1 full wave.
// Warp grid 2(M) x 4(N); warp tile 64x32.
__global__ void __launch_bounds__(256, 2) gauss_gemm(float* __restrict__ out) {
    extern __shared__ char smem[];
    const uint32_t sb = smem_u32(smem);
    const int tid  = threadIdx.x;
    const int warp = tid >> 5;
    const int lane = tid & 31;
    const int nblock = blockIdx.x;
    const int mblock = blockIdx.y;
    const int warp_m = warp >> 2;       // 0..1
    const int warp_n = warp & 3;        // 0..3

    // ---- per-thread cp.async plan: 1024 chunks/stage (A:512, B:512), 4/thread
    uint32_t dstoff[4];
    uint64_t srcoff[4];
    bool     isAj[4];
#pragma unroll
    for (int j = 0; j < 4; j++) {
        int ch = j * 256 + tid;
        bool a = ch < 512;
        int r = (ch & 511) >> 2;        // row 0..127
        int c = ch & 3;                 // 16B chunk in 64B stage-slice
        int grow = a ? (mblock * TM + r) : (nblock * TN + r);
        srcoff[j] = (uint64_t)grow * KROW_BYTES + (uint64_t)c * 16;
        dstoff[j] = (a ? 0u : (uint32_t)A_SMEM) + (uint32_t)(r * PITCH + c * 16);
        isAj[j] = a;
    }

    auto load_stage = [&](int s) {
        const int seg  = s >> 7;        // 0:Ehi*Whi 1:Elo*Whi 2:Ehi*Wlo
        const size_t koff = (size_t)(s & 127) * 64;
        const char* ab = (const char*)(seg == 1 ? g_Elo : g_Ehi) + koff;
        const char* bb = (const char*)(seg == 2 ? g_Wlo : g_Whi) + koff;
        const uint32_t stb = sb + (uint32_t)(s & 3) * STAGE_BYTES;
#pragma unroll
        for (int j = 0; j < 4; j++)
            cp_async16(stb + dstoff[j], (isAj[j] ? ab : bb) + srcoff[j]);
        cp_commit();
    };

    // ---- ldmatrix lane address components (byte offsets within stage)
    // A tile (16 rows x k16): lane -> row (l&15), k-chunk (l>>4)
    const uint32_t a_lane_off =
        (uint32_t)((warp_m * 64 + (lane & 15)) * PITCH + (lane >> 4) * 16);
    // B tile (n16 x k16): lanes 0-7:n0-7 c0, 8-15:n0-7 c1, 16-23:n8-15 c0, 24-31:n8-15 c1
    const uint32_t b_lane_off = (uint32_t)(A_SMEM +
        (warp_n * 32 + (lane & 7) + ((lane >> 4) & 1) * 8) * PITCH +
        ((lane >> 3) & 1) * 16);

    float acc[4][4][4];
#pragma unroll
    for (int mt = 0; mt < 4; mt++)
#pragma unroll
        for (int nt = 0; nt < 4; nt++)
#pragma unroll
            for (int q = 0; q < 4; q++) acc[mt][nt][q] = 0.0f;

    // prologue
    load_stage(0); load_stage(1); load_stage(2);

    for (int s = 0; s < NITER; s++) {
        cp_wait2();
        __syncthreads();
        if (s + 3 < NITER) load_stage(s + 3);
        else cp_commit();   // empty group keeps wait_group bookkeeping aligned

        const uint32_t stb = sb + (uint32_t)(s & 3) * STAGE_BYTES;
#pragma unroll
        for (int sub = 0; sub < 2; sub++) {       // two k16 slices per stage
            uint32_t afr[4][4];
            uint32_t bfr[2][4];
#pragma unroll
            for (int mt = 0; mt < 4; mt++)
                ldsm_x4(afr[mt], stb + a_lane_off + (uint32_t)(mt * 16 * PITCH + sub * 32));
#pragma unroll
            for (int bt = 0; bt < 2; bt++)
                ldsm_x4(bfr[bt], stb + b_lane_off + (uint32_t)(bt * 16 * PITCH + sub * 32));
#pragma unroll
            for (int mt = 0; mt < 4; mt++) {
#pragma unroll
                for (int nt = 0; nt < 4; nt++)
                    mma16816(acc[mt][nt], afr[mt], &bfr[nt >> 1][(nt & 1) * 2]);
            }
        }
    }

    // ---- epilogue: direct fp32 stores
    const int row0 = mblock * TM + warp_m * 64 + (lane >> 2);
    const int col0 = nblock * TN + warp_n * 32 + (lane & 3) * 2;
#pragma unroll
    for (int mt = 0; mt < 4; mt++) {
#pragma unroll
        for (int nt = 0; nt < 4; nt++) {
            float* p0 = out + (size_t)(row0 + mt * 16) * OSZ + col0 + nt * 8;
            float* p1 = p0 + 8 * OSZ;
            *reinterpret_cast<float2*>(p0) = make_float2(acc[mt][nt][0], acc[mt][nt][1]);
            *reinterpret_cast<float2*>(p1) = make_float2(acc[mt][nt][2], acc[mt][nt][3]);
        }
    }
}

// ---------------- launch ----------------
extern "C" void kernel_launch(void* const* d_in, const int* in_sizes, int n_in,
                              void* d_out, int out_size) {
    const float* x    = (const float*)d_in[0];  // [8192, 512]
    const float* w    = (const float*)d_in[1];  // [512, 512]
    const float* coef = (const float*)d_in[2];  // [512, 512, 8]
    float* out = (float*)d_out;                 // [8192, 512]

    prep_W<<<(OSZ * ISZ) / 256, 256>>>(w, coef);
    prep_E<<<(BATCH * ISZ) / 256, 256>>>(x);

    cudaFuncSetAttribute(gauss_gemm, cudaFuncAttributeMaxDynamicSharedMemorySize, SMEM_TOTAL);
    gauss_gemm<<<dim3(OSZ / TN, BATCH / TM), 256, SMEM_TOTAL>>>(out);
}

// round 10
// speedup vs baseline: 1.3204x; 1.3204x over previous
#include <cuda_runtime.h>
#include <cuda_bf16.h>
#include <cstdint>
#include <cstddef>

// ============================================================================
// CustomGaussianLayer as GEMM C[8192,512] = E[8192,4096] @ W2^T[4096,512],
// split-bf16 3-term (Ehi*Whi + Elo*Whi + Ehi*Wlo), K_eff = 12288.
// Baseline-ISA tensor cores (harness lowers to plain sm_103 PTX): mma.sync
// m16n8k16.bf16 + ldmatrix + cp.async 4-stage pipeline.
// R10: 64x64 warp tiles (4 warps/CTA) to cut smem crossbar traffic 33%
// (A fragments were read 4x by the old 2x4 warp grid, B 2x).
// ============================================================================

#define DINL __device__ __forceinline__

constexpr int BATCH = 8192;
constexpr int ISZ   = 512;
constexpr int OSZ   = 512;
constexpr int K1    = ISZ * 8;            // 4096
constexpr int KROW_BYTES = K1 * 2;        // 8192 bytes per row (bf16)

constexpr int TM = 128;
constexpr int TN = 128;
constexpr int KCH = 32;                   // K per stage (64 bytes per row)
constexpr int STAGES_PER_SEG = K1 / KCH;  // 128
constexpr int NITER = 3 * STAGES_PER_SEG; // 384
constexpr int PITCH = 80;                 // conflict-free smem row pitch
constexpr int A_SMEM = TM * PITCH;        // 10240
constexpr int STAGE_BYTES = 2 * A_SMEM;   // 20480
constexpr int NSTAGE = 4;
constexpr int SMEM_TOTAL = NSTAGE * STAGE_BYTES; // 81920
constexpr int NTHREADS = 128;             // 4 warps, 2x2 warp grid, 64x64 tiles

__device__ __nv_bfloat16 g_Ehi[(size_t)BATCH * K1];
__device__ __nv_bfloat16 g_Elo[(size_t)BATCH * K1];
__device__ __nv_bfloat16 g_Whi[(size_t)OSZ * K1];
__device__ __nv_bfloat16 g_Wlo[(size_t)OSZ * K1];

DINL uint32_t smem_u32(const void* p) {
    uint32_t a;
    asm("{ .reg .u64 t; cvta.to.shared.u64 t, %1; cvt.u32.u64 %0, t; }" : "=r"(a) : "l"(p));
    return a;
}

DINL void cp_async16(uint32_t dst, const void* src) {
    asm volatile("cp.async.cg.shared.global [%0], [%1], 16;" :: "r"(dst), "l"(src) : "memory");
}
DINL void cp_commit() { asm volatile("cp.async.commit_group;" ::: "memory"); }
DINL void cp_wait2()  { asm volatile("cp.async.wait_group 2;" ::: "memory"); }

DINL void ldsm_x4(uint32_t (&r)[4], uint32_t addr) {
    asm volatile("ldmatrix.sync.aligned.m8n8.x4.shared.b16 {%0,%1,%2,%3}, [%4];"
                 : "=r"(r[0]), "=r"(r[1]), "=r"(r[2]), "=r"(r[3]) : "r"(addr));
}

DINL void mma16816(float (&d)[4], const uint32_t (&a)[4], const uint32_t* b) {
    asm volatile(
        "mma.sync.aligned.m16n8k16.row.col.f32.bf16.bf16.f32 "
        "{%0,%1,%2,%3}, {%4,%5,%6,%7}, {%8,%9}, {%0,%1,%2,%3};"
        : "+f"(d[0]), "+f"(d[1]), "+f"(d[2]), "+f"(d[3])
        : "r"(a[0]), "r"(a[1]), "r"(a[2]), "r"(a[3]), "r"(b[0]), "r"(b[1]));
}

// ---------------- prep kernels (unchanged; ~32 us combined) ----------------
__global__ void prep_W(const float* __restrict__ w, const float* __restrict__ coef) {
    int idx = blockIdx.x * 256 + threadIdx.x;   // o*512 + i
    float wv = w[idx];
    const float4* cp = reinterpret_cast<const float4*>(coef + (size_t)idx * 8);
    float4 c0 = cp[0], c1 = cp[1];
    float v[8] = {c0.x, c0.y, c0.z, c0.w, c1.x, c1.y, c1.z, c1.w};
    unsigned short hi[8], lo[8];
#pragma unroll
    for (int g = 0; g < 8; g++) {
        float t = v[g] * wv;
        __nv_bfloat16 h = __float2bfloat16(t);
        float r = t - __bfloat162float(h);
        hi[g] = __bfloat16_as_ushort(h);
        lo[g] = __bfloat16_as_ushort(__float2bfloat16(r));
    }
    uint4 uh, ul;
    uh.x = hi[0] | ((uint32_t)hi[1] << 16); uh.y = hi[2] | ((uint32_t)hi[3] << 16);
    uh.z = hi[4] | ((uint32_t)hi[5] << 16); uh.w = hi[6] | ((uint32_t)hi[7] << 16);
    ul.x = lo[0] | ((uint32_t)lo[1] << 16); ul.y = lo[2] | ((uint32_t)lo[3] << 16);
    ul.z = lo[4] | ((uint32_t)lo[5] << 16); ul.w = lo[6] | ((uint32_t)lo[7] << 16);
    *reinterpret_cast<uint4*>(&g_Whi[(size_t)idx * 8]) = uh;
    *reinterpret_cast<uint4*>(&g_Wlo[(size_t)idx * 8]) = ul;
}

__global__ void prep_E(const float* __restrict__ x) {
    int idx = blockIdx.x * 256 + threadIdx.x;   // b*512 + i
    float xt = tanhf(x[idx]);
    unsigned short hi[8], lo[8];
#pragma unroll
    for (int g = 0; g < 8; g++) {
        float z = fmaf(7.0f, xt, 7.0f - 2.0f * (float)g);
        float e = __expf(-0.5f * z * z);
        __nv_bfloat16 h = __float2bfloat16(e);
        float r = e - __bfloat162float(h);
        hi[g] = __bfloat16_as_ushort(h);
        lo[g] = __bfloat16_as_ushort(__float2bfloat16(r));
    }
    uint4 uh, ul;
    uh.x = hi[0] | ((uint32_t)hi[1] << 16); uh.y = hi[2] | ((uint32_t)hi[3] << 16);
    uh.z = hi[4] | ((uint32_t)hi[5] << 16); uh.w = hi[6] | ((uint32_t)hi[7] << 16);
    ul.x = lo[0] | ((uint32_t)lo[1] << 16); ul.y = lo[2] | ((uint32_t)lo[3] << 16);
    ul.z = lo[4] | ((uint32_t)lo[5] << 16); ul.w = lo[6] | ((uint32_t)lo[7] << 16);
    *reinterpret_cast<uint4*>(&g_Ehi[(size_t)idx * 8]) = uh;
    *reinterpret_cast<uint4*>(&g_Elo[(size_t)idx * 8]) = ul;
}

// ---------------- GEMM kernel ----------------
// grid = (4, 64) = 256 CTAs, 128 threads, 2 CTAs/SM -> 1 wave.
// Warp grid 2(M) x 2(N); warp tile 64x64.
__global__ void __launch_bounds__(NTHREADS, 2) gauss_gemm(float* __restrict__ out) {
    extern __shared__ char smem[];
    const uint32_t sb = smem_u32(smem);
    const int tid  = threadIdx.x;
    const int warp = tid >> 5;
    const int lane = tid & 31;
    const int nblock = blockIdx.x;
    const int mblock = blockIdx.y;
    const int warp_m = warp >> 1;       // 0..1
    const int warp_n = warp & 1;        // 0..1

    // ---- cp.async plan: 1024 16B chunks/stage (A:512, B:512), 8 per thread
    uint32_t dstoff[8];
    uint64_t srcoff[8];
    bool     isAj[8];
#pragma unroll
    for (int j = 0; j < 8; j++) {
        int ch = j * NTHREADS + tid;
        bool a = ch < 512;
        int r = (ch & 511) >> 2;        // row 0..127
        int c = ch & 3;                 // 16B chunk in 64B stage-slice
        int grow = a ? (mblock * TM + r) : (nblock * TN + r);
        srcoff[j] = (uint64_t)grow * KROW_BYTES + (uint64_t)c * 16;
        dstoff[j] = (a ? 0u : (uint32_t)A_SMEM) + (uint32_t)(r * PITCH + c * 16);
        isAj[j] = a;
    }

    auto load_stage = [&](int s) {
        const int seg  = s >> 7;        // 0:Ehi*Whi 1:Elo*Whi 2:Ehi*Wlo
        const size_t koff = (size_t)(s & 127) * 64;
        const char* ab = (const char*)(seg == 1 ? g_Elo : g_Ehi) + koff;
        const char* bb = (const char*)(seg == 2 ? g_Wlo : g_Whi) + koff;
        const uint32_t stb = sb + (uint32_t)(s & 3) * STAGE_BYTES;
#pragma unroll
        for (int j = 0; j < 8; j++)
            cp_async16(stb + dstoff[j], (isAj[j] ? ab : bb) + srcoff[j]);
        cp_commit();
    };

    // ---- ldmatrix lane address components
    // A (16 rows x k16): lane -> row (l&15), k-chunk (l>>4)
    const uint32_t a_lane_off =
        (uint32_t)((warp_m * 64 + (lane & 15)) * PITCH + (lane >> 4) * 16);
    // B (n16 x k16): lanes 0-7:n0-7 c0, 8-15:n0-7 c1, 16-23:n8-15 c0, 24-31:n8-15 c1
    const uint32_t b_lane_off = (uint32_t)(A_SMEM +
        (warp_n * 64 + (lane & 7) + ((lane >> 4) & 1) * 8) * PITCH +
        ((lane >> 3) & 1) * 16);

    float acc[4][8][4];
#pragma unroll
    for (int mt = 0; mt < 4; mt++)
#pragma unroll
        for (int nt = 0; nt < 8; nt++)
#pragma unroll
            for (int q = 0; q < 4; q++) acc[mt][nt][q] = 0.0f;

    // prologue
    load_stage(0); load_stage(1); load_stage(2);

    for (int s = 0; s < NITER; s++) {
        cp_wait2();
        __syncthreads();
        if (s + 3 < NITER) load_stage(s + 3);
        else cp_commit();   // empty group keeps wait_group bookkeeping aligned

        const uint32_t stb = sb + (uint32_t)(s & 3) * STAGE_BYTES;
#pragma unroll
        for (int sub = 0; sub < 2; sub++) {       // two k16 slices per stage
            uint32_t afr[4][4];
            uint32_t bfr[4][4];
#pragma unroll
            for (int mt = 0; mt < 4; mt++)
                ldsm_x4(afr[mt], stb + a_lane_off + (uint32_t)(mt * 16 * PITCH + sub * 32));
#pragma unroll
            for (int bt = 0; bt < 4; bt++)
                ldsm_x4(bfr[bt], stb + b_lane_off + (uint32_t)(bt * 16 * PITCH + sub * 32));
#pragma unroll
            for (int mt = 0; mt < 4; mt++) {
#pragma unroll
                for (int nt = 0; nt < 8; nt++)
                    mma16816(acc[mt][nt], afr[mt], &bfr[nt >> 1][(nt & 1) * 2]);
            }
        }
    }

    // ---- epilogue: direct fp32 stores
    const int row0 = mblock * TM + warp_m * 64 + (lane >> 2);
    const int col0 = nblock * TN + warp_n * 64 + (lane & 3) * 2;
#pragma unroll
    for (int mt = 0; mt < 4; mt++) {
#pragma unroll
        for (int nt = 0; nt < 8; nt++) {
            float* p0 = out + (size_t)(row0 + mt * 16) * OSZ + col0 + nt * 8;
            float* p1 = p0 + 8 * OSZ;
            *reinterpret_cast<float2*>(p0) = make_float2(acc[mt][nt][0], acc[mt][nt][1]);
            *reinterpret_cast<float2*>(p1) = make_float2(acc[mt][nt][2], acc[mt][nt][3]);
        }
    }
}

// ---------------- launch ----------------
extern "C" void kernel_launch(void* const* d_in, const int* in_sizes, int n_in,
                              void* d_out, int out_size) {
    const float* x    = (const float*)d_in[0];  // [8192, 512]
    const float* w    = (const float*)d_in[1];  // [512, 512]
    const float* coef = (const float*)d_in[2];  // [512, 512, 8]
    float* out = (float*)d_out;                 // [8192, 512]

    prep_W<<<(OSZ * ISZ) / 256, 256>>>(w, coef);
    prep_E<<<(BATCH * ISZ) / 256, 256>>>(x);

    cudaFuncSetAttribute(gauss_gemm, cudaFuncAttributeMaxDynamicSharedMemorySize, SMEM_TOTAL);
    gauss_gemm<<<dim3(OSZ / TN, BATCH / TM), NTHREADS, SMEM_TOTAL>>>(out);
}

// round 15
// speedup vs baseline: 1.9044x; 1.4423x over previous
#include <cuda_runtime.h>
#include <cuda_fp16.h>
#include <cstdint>
#include <cstddef>

// ============================================================================
// CustomGaussianLayer as GEMM C[8192,512] = E[8192,4096] @ W2^T[4096,512].
// R11 numerics: fp16 2-segment. W2 split into fp16 hi+lo (exact to ~2^-21),
// E single fp16. out = E*Whi + E*Wlo over K_eff = 2*4096 = 8192.
// Error ~ E-rounding only: norm-rel ~ 2^-11/sqrt(3) ~ 2.8e-4 < 1e-3.
// Baseline-ISA tensor cores (harness lowers to plain sm_103 PTX): mma.sync
// m16n8k16.f16 + ldmatrix + cp.async 4-stage pipeline, 64x64 warp tiles.
// ============================================================================

#define DINL __device__ __forceinline__

constexpr int BATCH = 8192;
constexpr int ISZ   = 512;
constexpr int OSZ   = 512;
constexpr int K1    = ISZ * 8;            // 4096
constexpr int KROW_BYTES = K1 * 2;        // 8192 bytes per row (fp16)

constexpr int TM = 128;
constexpr int TN = 128;
constexpr int KCH = 32;                   // K per stage (64 bytes per row)
constexpr int STAGES_PER_SEG = K1 / KCH;  // 128
constexpr int NITER = 2 * STAGES_PER_SEG; // 256  (2 segments: E*Whi, E*Wlo)
constexpr int PITCH = 80;                 // conflict-free smem row pitch
constexpr int A_SMEM = TM * PITCH;        // 10240
constexpr int STAGE_BYTES = 2 * A_SMEM;   // 20480
constexpr int NSTAGE = 4;
constexpr int SMEM_TOTAL = NSTAGE * STAGE_BYTES; // 81920
constexpr int NTHREADS = 128;             // 4 warps, 2x2 warp grid, 64x64 tiles

__device__ __half g_E  [(size_t)BATCH * K1];   // 64 MB
__device__ __half g_Whi[(size_t)OSZ * K1];     // 4 MB
__device__ __half g_Wlo[(size_t)OSZ * K1];     // 4 MB

DINL uint32_t smem_u32(const void* p) {
    uint32_t a;
    asm("{ .reg .u64 t; cvta.to.shared.u64 t, %1; cvt.u32.u64 %0, t; }" : "=r"(a) : "l"(p));
    return a;
}

DINL void cp_async16(uint32_t dst, const void* src) {
    asm volatile("cp.async.cg.shared.global [%0], [%1], 16;" :: "r"(dst), "l"(src) : "memory");
}
DINL void cp_commit() { asm volatile("cp.async.commit_group;" ::: "memory"); }
DINL void cp_wait2()  { asm volatile("cp.async.wait_group 2;" ::: "memory"); }

DINL void ldsm_x4(uint32_t (&r)[4], uint32_t addr) {
    asm volatile("ldmatrix.sync.aligned.m8n8.x4.shared.b16 {%0,%1,%2,%3}, [%4];"
                 : "=r"(r[0]), "=r"(r[1]), "=r"(r[2]), "=r"(r[3]) : "r"(addr));
}

DINL void mma16816(float (&d)[4], const uint32_t (&a)[4], const uint32_t* b) {
    asm volatile(
        "mma.sync.aligned.m16n8k16.row.col.f32.f16.f16.f32 "
        "{%0,%1,%2,%3}, {%4,%5,%6,%7}, {%8,%9}, {%0,%1,%2,%3};"
        : "+f"(d[0]), "+f"(d[1]), "+f"(d[2]), "+f"(d[3])
        : "r"(a[0]), "r"(a[1]), "r"(a[2]), "r"(a[3]), "r"(b[0]), "r"(b[1]));
}

// ---------------- prep kernels ----------------
// W2[o, i*8+g] = coeff[o,i,g] * weights[o,i], exact fp16 hi/lo split.
__global__ void prep_W(const float* __restrict__ w, const float* __restrict__ coef) {
    int idx = blockIdx.x * 256 + threadIdx.x;   // o*512 + i
    float wv = w[idx];
    const float4* cp = reinterpret_cast<const float4*>(coef + (size_t)idx * 8);
    float4 c0 = cp[0], c1 = cp[1];
    float v[8] = {c0.x, c0.y, c0.z, c0.w, c1.x, c1.y, c1.z, c1.w};
    unsigned short hi[8], lo[8];
#pragma unroll
    for (int g = 0; g < 8; g++) {
        float t = v[g] * wv;
        __half h = __float2half_rn(t);
        float r = t - __half2float(h);
        hi[g] = __half_as_ushort(h);
        lo[g] = __half_as_ushort(__float2half_rn(r));
    }
    uint4 uh, ul;
    uh.x = hi[0] | ((uint32_t)hi[1] << 16); uh.y = hi[2] | ((uint32_t)hi[3] << 16);
    uh.z = hi[4] | ((uint32_t)hi[5] << 16); uh.w = hi[6] | ((uint32_t)hi[7] << 16);
    ul.x = lo[0] | ((uint32_t)lo[1] << 16); ul.y = lo[2] | ((uint32_t)lo[3] << 16);
    ul.z = lo[4] | ((uint32_t)lo[5] << 16); ul.w = lo[6] | ((uint32_t)lo[7] << 16);
    *reinterpret_cast<uint4*>(&g_Whi[(size_t)idx * 8]) = uh;
    *reinterpret_cast<uint4*>(&g_Wlo[(size_t)idx * 8]) = ul;
}

// E[b, i*8+g] = exp(-0.5*((tanh(x)-c_g)*7)^2), single fp16 (values in [0,1]).
__global__ void prep_E(const float* __restrict__ x) {
    int idx = blockIdx.x * 256 + threadIdx.x;   // b*512 + i
    float xt = tanhf(x[idx]);
    unsigned short h[8];
#pragma unroll
    for (int g = 0; g < 8; g++) {
        float z = fmaf(7.0f, xt, 7.0f - 2.0f * (float)g);
        float e = __expf(-0.5f * z * z);
        h[g] = __half_as_ushort(__float2half_rn(e));
    }
    uint4 uh;
    uh.x = h[0] | ((uint32_t)h[1] << 16); uh.y = h[2] | ((uint32_t)h[3] << 16);
    uh.z = h[4] | ((uint32_t)h[5] << 16); uh.w = h[6] | ((uint32_t)h[7] << 16);
    *reinterpret_cast<uint4*>(&g_E[(size_t)idx * 8]) = uh;
}

// ---------------- GEMM kernel ----------------
// grid = (4, 64) = 256 CTAs, 128 threads, 2 CTAs/SM -> 1 wave.
// Warp grid 2(M) x 2(N); warp tile 64x64.
__global__ void __launch_bounds__(NTHREADS, 2) gauss_gemm(float* __restrict__ out) {
    extern __shared__ char smem[];
    const uint32_t sb = smem_u32(smem);
    const int tid  = threadIdx.x;
    const int warp = tid >> 5;
    const int lane = tid & 31;
    const int nblock = blockIdx.x;
    const int mblock = blockIdx.y;
    const int warp_m = warp >> 1;       // 0..1
    const int warp_n = warp & 1;        // 0..1

    // ---- cp.async plan: 1024 16B chunks/stage (A:512, B:512), 8 per thread
    uint32_t dstoff[8];
    uint64_t srcoff[8];
    bool     isAj[8];
#pragma unroll
    for (int j = 0; j < 8; j++) {
        int ch = j * NTHREADS + tid;
        bool a = ch < 512;
        int r = (ch & 511) >> 2;        // row 0..127
        int c = ch & 3;                 // 16B chunk in 64B stage-slice
        int grow = a ? (mblock * TM + r) : (nblock * TN + r);
        srcoff[j] = (uint64_t)grow * KROW_BYTES + (uint64_t)c * 16;
        dstoff[j] = (a ? 0u : (uint32_t)A_SMEM) + (uint32_t)(r * PITCH + c * 16);
        isAj[j] = a;
    }

    auto load_stage = [&](int s) {
        const int seg  = s >> 7;        // 0: E*Whi, 1: E*Wlo
        const size_t koff = (size_t)(s & 127) * 64;
        const char* ab = (const char*)g_E + koff;
        const char* bb = (const char*)(seg ? g_Wlo : g_Whi) + koff;
        const uint32_t stb = sb + (uint32_t)(s & 3) * STAGE_BYTES;
#pragma unroll
        for (int j = 0; j < 8; j++)
            cp_async16(stb + dstoff[j], (isAj[j] ? ab : bb) + srcoff[j]);
        cp_commit();
    };

    // ---- ldmatrix lane address components
    // A (16 rows x k16): lane -> row (l&15), k-chunk (l>>4)
    const uint32_t a_lane_off =
        (uint32_t)((warp_m * 64 + (lane & 15)) * PITCH + (lane >> 4) * 16);
    // B (n16 x k16): lanes 0-7:n0-7 c0, 8-15:n0-7 c1, 16-23:n8-15 c0, 24-31:n8-15 c1
    const uint32_t b_lane_off = (uint32_t)(A_SMEM +
        (warp_n * 64 + (lane & 7) + ((lane >> 4) & 1) * 8) * PITCH +
        ((lane >> 3) & 1) * 16);

    float acc[4][8][4];
#pragma unroll
    for (int mt = 0; mt < 4; mt++)
#pragma unroll
        for (int nt = 0; nt < 8; nt++)
#pragma unroll
            for (int q = 0; q < 4; q++) acc[mt][nt][q] = 0.0f;

    // prologue
    load_stage(0); load_stage(1); load_stage(2);

    for (int s = 0; s < NITER; s++) {
        cp_wait2();
        __syncthreads();
        if (s + 3 < NITER) load_stage(s + 3);
        else cp_commit();   // empty group keeps wait_group bookkeeping aligned

        const uint32_t stb = sb + (uint32_t)(s & 3) * STAGE_BYTES;
#pragma unroll
        for (int sub = 0; sub < 2; sub++) {       // two k16 slices per stage
            uint32_t afr[4][4];
            uint32_t bfr[4][4];
#pragma unroll
            for (int mt = 0; mt < 4; mt++)
                ldsm_x4(afr[mt], stb + a_lane_off + (uint32_t)(mt * 16 * PITCH + sub * 32));
#pragma unroll
            for (int bt = 0; bt < 4; bt++)
                ldsm_x4(bfr[bt], stb + b_lane_off + (uint32_t)(bt * 16 * PITCH + sub * 32));
#pragma unroll
            for (int mt = 0; mt < 4; mt++) {
#pragma unroll
                for (int nt = 0; nt < 8; nt++)
                    mma16816(acc[mt][nt], afr[mt], &bfr[nt >> 1][(nt & 1) * 2]);
            }
        }
    }

    // ---- epilogue: direct fp32 stores
    const int row0 = mblock * TM + warp_m * 64 + (lane >> 2);
    const int col0 = nblock * TN + warp_n * 64 + (lane & 3) * 2;
#pragma unroll
    for (int mt = 0; mt < 4; mt++) {
#pragma unroll
        for (int nt = 0; nt < 8; nt++) {
            float* p0 = out + (size_t)(row0 + mt * 16) * OSZ + col0 + nt * 8;
            float* p1 = p0 + 8 * OSZ;
            *reinterpret_cast<float2*>(p0) = make_float2(acc[mt][nt][0], acc[mt][nt][1]);
            *reinterpret_cast<float2*>(p1) = make_float2(acc[mt][nt][2], acc[mt][nt][3]);
        }
    }
}

// ---------------- launch ----------------
extern "C" void kernel_launch(void* const* d_in, const int* in_sizes, int n_in,
                              void* d_out, int out_size) {
    const float* x    = (const float*)d_in[0];  // [8192, 512]
    const float* w    = (const float*)d_in[1];  // [512, 512]
    const float* coef = (const float*)d_in[2];  // [512, 512, 8]
    float* out = (float*)d_out;                 // [8192, 512]

    prep_W<<<(OSZ * ISZ) / 256, 256>>>(w, coef);
    prep_E<<<(BATCH * ISZ) / 256, 256>>>(x);

    cudaFuncSetAttribute(gauss_gemm, cudaFuncAttributeMaxDynamicSharedMemorySize, SMEM_TOTAL);
    gauss_gemm<<<dim3(OSZ / TN, BATCH / TM), NTHREADS, SMEM_TOTAL>>>(out);
}